// round 16
// baseline (speedup 1.0000x reference)
#include <cuda_runtime.h>
#include <math.h>
#include <stdint.h>

#define HH 512
#define WW 1024
#define GRID_N 512
#define BINS (GRID_N * GRID_N)      // 262144 bins per histogram
#define WPH (BINS / 2)               // 131072 u32 words per histogram (2 u16 bins/word)
#define NB 16                        // batch
#define NPIX (HH * WW)               // 524288 per batch item
#define NHIST (2 * 3 * NB)           // 96
#define LOSS_BLOCKS (64 * 48)        // k_loss grid size (for completion ticket)

// magic rounding: fmaf(d, s, 2^23 + 256) -> bits = 0x4B000000 + rn(d*s + 256)
#define MAGICF 8388864.0f
#define BITS_K 0x4B000000u
#define BITS_HI 0x4B0001FFu          // bin <= 511

// 16-bit counters packed 2-per-u32: 48MB total. Static arrays start zeroed at
// module load; k_loss re-zeroes every word it reads, so each kernel_launch
// sequence begins with zeroed histograms (no dedicated zero kernel).
__device__ __align__(16) unsigned int g_hist[2][3][NB][WPH];
__device__ float  g_tabA[HH];                 // cos(theta)
__device__ float  g_tabB[HH];                 // -sin(theta)*25.6
__device__ __align__(16) float2 g_tabCD[WW];  // (cos(phi)*25.6, sin(phi)*25.6)
__device__ unsigned int g_maxc[NHIST];        // per-histogram raw max count
__device__ int    g_cmax[3];                  // float bits of per-plane max|diff|
__device__ double g_total;
__device__ unsigned int g_done;               // k_loss completion ticket

// ------- init: trig tables (fp64, spread over 6 SMs) + accumulators -------
__global__ void k_init_tables() {
    int b = blockIdx.x;               // 6 blocks x 256 threads
    int t = threadIdx.x;
    if (b < 2) {                      // theta rows: 2 blocks x 256 = 512
        int i = b * 256 + t;
        float th = -3.14159265358979f * ((float)i / 511.0f - 0.5f);
        double ct = cos((double)th), st = sin((double)th);
        g_tabA[i] = (float)ct;
        g_tabB[i] = (float)(-st * 25.6);
    } else {                          // phi cols: 4 blocks x 256 = 1024
        int j = (b - 2) * 256 + t;
        float ph = 3.14159265358979f * (2.0f * (float)j / 1023.0f - 1.0f);
        double cp = cos((double)ph), sp = sin((double)ph);
        g_tabCD[j] = make_float2((float)(cp * 25.6), (float)(sp * 25.6));
    }
    if (b == 0) {
        if (t < NHIST) g_maxc[t] = 0u;
        if (t < 3) g_cmax[t] = 0;
        if (t == 0) { g_total = 0.0; g_done = 0u; }
    }
}

// ---------------- scatter: 16 pixels per thread, 3 plane atomics per pixel ----
// Occupancy experiment: __launch_bounds__(256, 8) caps regs at 32/thread so 8
// CTAs (64 warps) fit per SM instead of the 40-reg/6-CTA/48-warp config. If the
// RED path is queue/latency-limited (no unit saturated in ncu), the extra
// in-flight atomics convert to speed; if it's a pure per-lane floor, neutral.
// Depth loads use __ldcs (evict-first) so the 64MB depth stream does not evict
// the 48MB histogram set from L2. No fences/tickets here (R14: +122us).
__global__ void __launch_bounds__(256, 8) k_scatter(const float* __restrict__ pred,
                                                    const float* __restrict__ gt) {
    const int t = blockIdx.y;                         // 0 = pred, 1 = gt
    const float* __restrict__ src = t ? gt : pred;
    unsigned int tid  = blockIdx.x * 256u + threadIdx.x;
    unsigned int pix0 = tid * 16u;                        // linear pixel index
    unsigned int b    = pix0 >> 19;                       // / 524288
    unsigned int inb  = pix0 & (NPIX - 1);
    unsigned int i    = inb >> 10;
    unsigned int j0   = inb & 1023u;                      // multiple of 16

    float  a  = g_tabA[i];
    float  wb = g_tabB[i];

    unsigned int* __restrict__ h0 = &g_hist[t][0][b][0];  // horizontal: (x=u, y=v)
    unsigned int* __restrict__ h1 = &g_hist[t][1][b][0];  // vertical:   (x=u, y=w)
    unsigned int* __restrict__ h2 = &g_hist[t][2][b][0];  // lateral:    (x=v, y=w)

#pragma unroll
    for (int q = 0; q < 4; q++) {                         // 4 quads of 4 pixels
        float4 d4  = __ldcs((const float4*)(src + pix0 + q * 4));  // streaming
        float4 cdA = *(const float4*)(&g_tabCD[j0 + q * 4]);
        float4 cdB = *(const float4*)(&g_tabCD[j0 + q * 4 + 2]);
        float ds[4] = {d4.x, d4.y, d4.z, d4.w};
        float cs[4] = {cdA.x, cdA.z, cdB.x, cdB.z};
        float ss[4] = {cdA.y, cdA.w, cdB.y, cdB.w};
#pragma unroll
        for (int k = 0; k < 4; k++) {
            float d  = ds[k];
            float us = cs[k] * a;
            float vs = ss[k] * a;
            unsigned int bu = min(__float_as_uint(fmaf(d, us, MAGICF)), BITS_HI) - BITS_K;
            unsigned int bv = min(__float_as_uint(fmaf(d, vs, MAGICF)), BITS_HI) - BITS_K;
            unsigned int bw = min(__float_as_uint(fmaf(d, wb, MAGICF)), BITS_HI) - BITS_K;
            unsigned int aU = 1u << ((bu & 1u) << 4);
            unsigned int aV = 1u << ((bv & 1u) << 4);
            atomicAdd(h0 + ((bv << 8) + (bu >> 1)), aU);   // density[y=v, x=u]
            atomicAdd(h1 + ((bw << 8) + (bu >> 1)), aU);   // density[y=w, x=u]
            atomicAdd(h2 + ((bw << 8) + (bv >> 1)), aV);   // density[y=w, x=v]
        }
    }
}

// ---------------- per-histogram max (parallel: 8 slices per histogram) ----------------
__global__ void __launch_bounds__(256) k_max() {
    int h = blockIdx.x;               // 0..95 == flat [t][s][b]
    int slice = blockIdx.y;           // 0..7
    const uint4* p = (const uint4*)((&g_hist[0][0][0][0]) + (size_t)h * WPH)
                     + slice * (WPH / 4 / 8);
    unsigned int m = 0;
#pragma unroll
    for (int r = 0; r < 16; r++) {    // 4096 uint4 per block = 256*16
        uint4 v = p[r * 256 + threadIdx.x];
        m = __vmaxu2(m, __vmaxu2(__vmaxu2(v.x, v.y), __vmaxu2(v.z, v.w)));
    }
    m = max(m & 0xFFFFu, m >> 16);
    __shared__ unsigned int sm[256];
    sm[threadIdx.x] = m;
    __syncthreads();
    for (int s = 128; s > 0; s >>= 1) {
        if (threadIdx.x < s) sm[threadIdx.x] = max(sm[threadIdx.x], sm[threadIdx.x + s]);
        __syncthreads();
    }
    if (threadIdx.x == 0) atomicMax(&g_maxc[h], sm[0]);
}

// |min(p,100)/mp - min(g,100)/mg| for both u16 halves of a packed word
__device__ __forceinline__ float2 diff2(unsigned int pw, unsigned int gw,
                                        float rp, float rg) {
    unsigned int pc = __vminu2(pw, 0x00640064u);
    unsigned int gc = __vminu2(gw, 0x00640064u);
    float2 r;
    r.x = fabsf((float)(pc & 0xFFFFu) * rp - (float)(gc & 0xFFFFu) * rg);
    r.y = fabsf((float)(pc >> 16)     * rp - (float)(gc >> 16)     * rg);
    return r;
}

// ---------------- per-plane max |diff| ----------------
__global__ void __launch_bounds__(256) k_diffmax() {
    int pair = blockIdx.y;            // 0..47 == s*16 + b
    int s = pair >> 4, bb = pair & 15;
    const uint4* hp = (const uint4*)&g_hist[0][s][bb][0];
    const uint4* hg = (const uint4*)&g_hist[1][s][bb][0];
    float rp = 1.0f / (float)min(g_maxc[(0 * 3 + s) * NB + bb], 100u);
    float rg = 1.0f / (float)min(g_maxc[(1 * 3 + s) * NB + bb], 100u);
    float m = 0.0f;
    int base = blockIdx.x * 512 + threadIdx.x;      // 64 blocks * 512 uint4 = 32768
#pragma unroll
    for (int r = 0; r < 2; r++) {
        int k = base + r * 256;
        uint4 p = hp[k], g = hg[k];
        float2 a0 = diff2(p.x, g.x, rp, rg);
        float2 a1 = diff2(p.y, g.y, rp, rg);
        float2 a2 = diff2(p.z, g.z, rp, rg);
        float2 a3 = diff2(p.w, g.w, rp, rg);
        m = fmaxf(m, fmaxf(fmaxf(fmaxf(a0.x, a0.y), fmaxf(a1.x, a1.y)),
                           fmaxf(fmaxf(a2.x, a2.y), fmaxf(a3.x, a3.y))));
    }
    __shared__ float sm[256];
    sm[threadIdx.x] = m;
    __syncthreads();
    for (int t = 128; t > 0; t >>= 1) {
        if (threadIdx.x < t) sm[threadIdx.x] = fmaxf(sm[threadIdx.x], sm[threadIdx.x + t]);
        __syncthreads();
    }
    if (threadIdx.x == 0) atomicMax(&g_cmax[s], __float_as_int(sm[0]));  // nonneg floats
}

// ---- berHu sum + re-zero histograms + fused finalization (arrival ticket) ----
// k_loss is the last reader of g_hist: after loading each uint4 it stores zeros
// back (hits L2 since __ldcs keeps the set resident), so the next replay starts
// from zeroed histograms and the dedicated zero kernel is eliminated.
__global__ void __launch_bounds__(256) k_loss(float* __restrict__ out) {
    int pair = blockIdx.y;
    int s = pair >> 4, bb = pair & 15;
    uint4* hp = (uint4*)&g_hist[0][s][bb][0];
    uint4* hg = (uint4*)&g_hist[1][s][bb][0];
    float rp = 1.0f / (float)min(g_maxc[(0 * 3 + s) * NB + bb], 100u);
    float rg = 1.0f / (float)min(g_maxc[(1 * 3 + s) * NB + bb], 100u);
    float c = 0.2f * __int_as_float(g_cmax[s]);
    float cc = c * c;
    float r2c = (c > 0.0f) ? (0.5f / c) : 0.0f;
    float sum = 0.0f;
    const uint4 z = make_uint4(0u, 0u, 0u, 0u);
    int base = blockIdx.x * 512 + threadIdx.x;
#pragma unroll
    for (int r = 0; r < 2; r++) {
        int k = base + r * 256;
        uint4 p = hp[k], g = hg[k];
        hp[k] = z;                                  // re-zero for next replay
        hg[k] = z;
        float2 a0 = diff2(p.x, g.x, rp, rg);
        float2 a1 = diff2(p.y, g.y, rp, rg);
        float2 a2 = diff2(p.z, g.z, rp, rg);
        float2 a3 = diff2(p.w, g.w, rp, rg);
        float dv[8] = {a0.x, a0.y, a1.x, a1.y, a2.x, a2.y, a3.x, a3.y};
#pragma unroll
        for (int q = 0; q < 8; q++) {
            float d = dv[q];
            sum += (d <= c) ? d : fmaf(d, d, cc) * r2c;
        }
    }
    __shared__ float sm[256];
    sm[threadIdx.x] = sum;
    __syncthreads();
    for (int t = 128; t > 0; t >>= 1) {
        if (threadIdx.x < t) sm[threadIdx.x] += sm[threadIdx.x + t];
        __syncthreads();
    }
    if (threadIdx.x == 0) {
        atomicAdd(&g_total, (double)sm[0]);
        __threadfence();
        unsigned int ticket = atomicAdd(&g_done, 1u);
        if (ticket == LOSS_BLOCKS - 1) {              // last CTA finalizes
            double tot = *((volatile double*)&g_total);
            out[0] = (float)(tot / (double)((size_t)NB * BINS));
            g_done = 0u;                              // re-arm for next replay
        }
    }
}

extern "C" void kernel_launch(void* const* d_in, const int* in_sizes, int n_in,
                              void* d_out, int out_size) {
    const float* pred = (const float*)d_in[0];
    const float* gt   = (const float*)d_in[1];

    k_init_tables<<<6, 256>>>();
    k_scatter<<<dim3(2048, 2), 256>>>(pred, gt);
    k_max<<<dim3(96, 8), 256>>>();
    k_diffmax<<<dim3(64, 48), 256>>>();
    k_loss<<<dim3(64, 48), 256>>>((float*)d_out);
}

// round 17
// speedup vs baseline: 1.0197x; 1.0197x over previous
#include <cuda_runtime.h>
#include <math.h>
#include <stdint.h>

#define HH 512
#define WW 1024
#define GRID_N 512
#define BINS (GRID_N * GRID_N)      // 262144 bins per histogram
#define WPH (BINS / 2)               // 131072 u32 words per histogram (2 u16 bins/word)
#define NB 16                        // batch
#define NPIX (HH * WW)               // 524288 per batch item
#define NHIST (2 * 3 * NB)           // 96
#define POST_BLOCKS (8 * 48)         // k_post grid; MUST be <= resident capacity

// magic rounding: fmaf(d, s, 2^23 + 256) -> bits = 0x4B000000 + rn(d*s + 256)
#define MAGICF 8388864.0f
#define BITS_K 0x4B000000u
#define BITS_HI 0x4B0001FFu          // bin <= 511

// 16-bit counters packed 2-per-u32: 48MB total. Static arrays start zeroed at
// module load; k_post phase 3 re-zeroes every word it reads, so each
// kernel_launch sequence begins with zeroed histograms.
__device__ __align__(16) unsigned int g_hist[2][3][NB][WPH];
__device__ float  g_tabA[HH];                 // cos(theta)
__device__ float  g_tabB[HH];                 // -sin(theta)*25.6
__device__ __align__(16) float2 g_tabCD[WW];  // (cos(phi)*25.6, sin(phi)*25.6)
__device__ unsigned int g_maxc[NHIST];        // per-histogram raw max count
__device__ int    g_cmax[3];                  // float bits of per-plane max|diff|
__device__ double g_total;
__device__ unsigned int g_bar1, g_bar2;       // soft grid barriers
__device__ unsigned int g_done;               // completion ticket

// ------- init: trig tables (fp64, spread over 6 SMs) + accumulators -------
__global__ void k_init_tables() {
    int b = blockIdx.x;               // 6 blocks x 256 threads
    int t = threadIdx.x;
    if (b < 2) {                      // theta rows: 2 blocks x 256 = 512
        int i = b * 256 + t;
        float th = -3.14159265358979f * ((float)i / 511.0f - 0.5f);
        double ct = cos((double)th), st = sin((double)th);
        g_tabA[i] = (float)ct;
        g_tabB[i] = (float)(-st * 25.6);
    } else {                          // phi cols: 4 blocks x 256 = 1024
        int j = (b - 2) * 256 + t;
        float ph = 3.14159265358979f * (2.0f * (float)j / 1023.0f - 1.0f);
        double cp = cos((double)ph), sp = sin((double)ph);
        g_tabCD[j] = make_float2((float)(cp * 25.6), (float)(sp * 25.6));
    }
    if (b == 0) {
        if (t < NHIST) g_maxc[t] = 0u;
        if (t < 3) g_cmax[t] = 0;
        if (t == 0) { g_total = 0.0; g_bar1 = 0u; g_bar2 = 0u; g_done = 0u; }
    }
}

// ---------------- scatter: 16 pixels per thread, 3 plane atomics per pixel ----
// At the L1TEX/LTS spread-RED per-lane throughput floor (R16 experiment: extra
// occupancy is neutral). Depth loads use __ldcs (evict-first) so the 64MB depth
// stream does not evict the 48MB histogram set from L2. No fences/tickets here
// — end-of-CTA membar drains in-flight REDs and serializes (R14: +122us).
__global__ void __launch_bounds__(256) k_scatter(const float* __restrict__ pred,
                                                 const float* __restrict__ gt) {
    const int t = blockIdx.y;                         // 0 = pred, 1 = gt
    const float* __restrict__ src = t ? gt : pred;
    unsigned int tid  = blockIdx.x * 256u + threadIdx.x;
    unsigned int pix0 = tid * 16u;                        // linear pixel index
    unsigned int b    = pix0 >> 19;                       // / 524288
    unsigned int inb  = pix0 & (NPIX - 1);
    unsigned int i    = inb >> 10;
    unsigned int j0   = inb & 1023u;                      // multiple of 16

    float  a  = g_tabA[i];
    float  wb = g_tabB[i];

    unsigned int* __restrict__ h0 = &g_hist[t][0][b][0];  // horizontal: (x=u, y=v)
    unsigned int* __restrict__ h1 = &g_hist[t][1][b][0];  // vertical:   (x=u, y=w)
    unsigned int* __restrict__ h2 = &g_hist[t][2][b][0];  // lateral:    (x=v, y=w)

#pragma unroll
    for (int q = 0; q < 4; q++) {                         // 4 quads of 4 pixels
        float4 d4  = __ldcs((const float4*)(src + pix0 + q * 4));  // streaming
        float4 cdA = *(const float4*)(&g_tabCD[j0 + q * 4]);
        float4 cdB = *(const float4*)(&g_tabCD[j0 + q * 4 + 2]);
        float ds[4] = {d4.x, d4.y, d4.z, d4.w};
        float cs[4] = {cdA.x, cdA.z, cdB.x, cdB.z};
        float ss[4] = {cdA.y, cdA.w, cdB.y, cdB.w};
#pragma unroll
        for (int k = 0; k < 4; k++) {
            float d  = ds[k];
            float us = cs[k] * a;
            float vs = ss[k] * a;
            unsigned int bu = min(__float_as_uint(fmaf(d, us, MAGICF)), BITS_HI) - BITS_K;
            unsigned int bv = min(__float_as_uint(fmaf(d, vs, MAGICF)), BITS_HI) - BITS_K;
            unsigned int bw = min(__float_as_uint(fmaf(d, wb, MAGICF)), BITS_HI) - BITS_K;
            unsigned int aU = 1u << ((bu & 1u) << 4);
            unsigned int aV = 1u << ((bv & 1u) << 4);
            atomicAdd(h0 + ((bv << 8) + (bu >> 1)), aU);   // density[y=v, x=u]
            atomicAdd(h1 + ((bw << 8) + (bu >> 1)), aU);   // density[y=w, x=u]
            atomicAdd(h2 + ((bw << 8) + (bv >> 1)), aV);   // density[y=w, x=v]
        }
    }
}

// |min(p,100)/mp - min(g,100)/mg| for both u16 halves of a packed word
__device__ __forceinline__ float2 diff2(unsigned int pw, unsigned int gw,
                                        float rp, float rg) {
    unsigned int pc = __vminu2(pw, 0x00640064u);
    unsigned int gc = __vminu2(gw, 0x00640064u);
    float2 r;
    r.x = fabsf((float)(pc & 0xFFFFu) * rp - (float)(gc & 0xFFFFu) * rg);
    r.y = fabsf((float)(pc >> 16)     * rp - (float)(gc >> 16)     * rg);
    return r;
}

// Soft grid barrier: safe because POST_BLOCKS (384) <= guaranteed resident
// capacity (launch_bounds(256,8) caps regs at 32 -> 8 CTAs/SM -> 1184 blocks).
__device__ __forceinline__ void soft_bar(unsigned int* cnt) {
    __syncthreads();
    if (threadIdx.x == 0) {
        atomicAdd(cnt, 1u);
        while (*((volatile unsigned int*)cnt) < POST_BLOCKS) __nanosleep(64);
    }
    __syncthreads();
}

// ---- fused post-pass: hist-max -> plane diff-max -> berHu sum + re-zero ----
// One persistent kernel, 3 phases over the same L2-resident slices, replacing
// the k_max / k_diffmax / k_loss launch chain (saves 2 launches + ramps).
__global__ void __launch_bounds__(256, 8) k_post(float* __restrict__ out) {
    const int pair = blockIdx.y;              // 0..47 == s*16 + bb
    const int s = pair >> 4, bb = pair & 15;
    const int ip = (0 * 3 + s) * NB + bb;     // pred hist index
    const int ig = (1 * 3 + s) * NB + bb;     // gt hist index
    uint4* hp = (uint4*)&g_hist[0][s][bb][0];
    uint4* hg = (uint4*)&g_hist[1][s][bb][0];
    const int base = blockIdx.x * 4096;       // 8 slices x 4096 uint4 = WPH/4
    __shared__ unsigned int smu[256];
    __shared__ float smf[256];

    // ---- phase 1: per-histogram raw max ----
    unsigned int mp = 0, mg = 0;
#pragma unroll
    for (int r = 0; r < 16; r++) {
        int k = base + r * 256 + threadIdx.x;
        uint4 a = hp[k], b = hg[k];
        mp = __vmaxu2(mp, __vmaxu2(__vmaxu2(a.x, a.y), __vmaxu2(a.z, a.w)));
        mg = __vmaxu2(mg, __vmaxu2(__vmaxu2(b.x, b.y), __vmaxu2(b.z, b.w)));
    }
    mp = max(mp & 0xFFFFu, mp >> 16);         // <= 65535
    mg = max(mg & 0xFFFFu, mg >> 16);
    smu[threadIdx.x] = (mp << 16) | mg;       // packed dual reduce
    __syncthreads();
    for (int t = 128; t > 0; t >>= 1) {
        if (threadIdx.x < t) smu[threadIdx.x] = __vmaxu2(smu[threadIdx.x], smu[threadIdx.x + t]);
        __syncthreads();
    }
    if (threadIdx.x == 0) {
        unsigned int red = smu[0];
        atomicMax(&g_maxc[ip], red >> 16);
        atomicMax(&g_maxc[ig], red & 0xFFFFu);
        __threadfence();                      // 2 atomics in flight: cheap drain
    }
    soft_bar(&g_bar1);

    // ---- phase 2: per-plane max |diff| ----
    float rp = 1.0f / (float)min(g_maxc[ip], 100u);
    float rg = 1.0f / (float)min(g_maxc[ig], 100u);
    float m = 0.0f;
#pragma unroll
    for (int r = 0; r < 16; r++) {
        int k = base + r * 256 + threadIdx.x;
        uint4 p = hp[k], g = hg[k];
        float2 a0 = diff2(p.x, g.x, rp, rg);
        float2 a1 = diff2(p.y, g.y, rp, rg);
        float2 a2 = diff2(p.z, g.z, rp, rg);
        float2 a3 = diff2(p.w, g.w, rp, rg);
        m = fmaxf(m, fmaxf(fmaxf(fmaxf(a0.x, a0.y), fmaxf(a1.x, a1.y)),
                           fmaxf(fmaxf(a2.x, a2.y), fmaxf(a3.x, a3.y))));
    }
    smf[threadIdx.x] = m;
    __syncthreads();
    for (int t = 128; t > 0; t >>= 1) {
        if (threadIdx.x < t) smf[threadIdx.x] = fmaxf(smf[threadIdx.x], smf[threadIdx.x + t]);
        __syncthreads();
    }
    if (threadIdx.x == 0) {
        atomicMax(&g_cmax[s], __float_as_int(smf[0]));   // nonneg floats
        __threadfence();
    }
    soft_bar(&g_bar2);

    // ---- phase 3: berHu sum + re-zero ----
    float c = 0.2f * __int_as_float(g_cmax[s]);
    float cc = c * c;
    float r2c = (c > 0.0f) ? (0.5f / c) : 0.0f;
    float sum = 0.0f;
    const uint4 z = make_uint4(0u, 0u, 0u, 0u);
#pragma unroll
    for (int r = 0; r < 16; r++) {
        int k = base + r * 256 + threadIdx.x;
        uint4 p = hp[k], g = hg[k];
        hp[k] = z;                            // re-zero for next replay
        hg[k] = z;
        float2 a0 = diff2(p.x, g.x, rp, rg);
        float2 a1 = diff2(p.y, g.y, rp, rg);
        float2 a2 = diff2(p.z, g.z, rp, rg);
        float2 a3 = diff2(p.w, g.w, rp, rg);
        float dv[8] = {a0.x, a0.y, a1.x, a1.y, a2.x, a2.y, a3.x, a3.y};
#pragma unroll
        for (int q = 0; q < 8; q++) {
            float d = dv[q];
            sum += (d <= c) ? d : fmaf(d, d, cc) * r2c;
        }
    }
    smf[threadIdx.x] = sum;
    __syncthreads();
    for (int t = 128; t > 0; t >>= 1) {
        if (threadIdx.x < t) smf[threadIdx.x] += smf[threadIdx.x + t];
        __syncthreads();
    }
    if (threadIdx.x == 0) {
        atomicAdd(&g_total, (double)smf[0]);
        __threadfence();
        unsigned int ticket = atomicAdd(&g_done, 1u);
        if (ticket == POST_BLOCKS - 1) {      // last block finalizes
            double tot = *((volatile double*)&g_total);
            out[0] = (float)(tot / (double)((size_t)NB * BINS));
        }
    }
}

extern "C" void kernel_launch(void* const* d_in, const int* in_sizes, int n_in,
                              void* d_out, int out_size) {
    const float* pred = (const float*)d_in[0];
    const float* gt   = (const float*)d_in[1];

    k_init_tables<<<6, 256>>>();
    k_scatter<<<dim3(2048, 2), 256>>>(pred, gt);
    k_post<<<dim3(8, 48), 256>>>((float*)d_out);
}